// round 4
// baseline (speedup 1.0000x reference)
#include <cuda_runtime.h>
#include <math.h>

// Problem constants
#define BB   4
#define NN   2000
#define KKN  30
#define DD   128
#define DIN  256
#define HH   4
#define ROWS (BB*NN)           // 8000

#define SCALE 0.17677669529663687f   // 1/sqrt(32)

// Scratch (static device globals: no runtime allocation)
__device__ float g_Qp  [(size_t)ROWS*HH*DIN];  // 32 MB
__device__ float g_Eagg[(size_t)ROWS*HH*DIN];  // 32 MB
__device__ float g_hu  [(size_t)ROWS*DD];      // 4 MB

// ---------------------------------------------------------------------------
// Kernel 1: per row r: Q[j] = sum_d hV[r][d]*WQ[j][d]
//           Qp[h][c] = SCALE * sum_{j<32} Q[h*32+j]*WK[h*32+j][c]
// Block: 16 rows, 256 threads.
// ---------------------------------------------------------------------------
__global__ __launch_bounds__(256) void k1_qp(const float* __restrict__ hV,
                                             const float* __restrict__ WQ,
                                             const float* __restrict__ WK)
{
    __shared__ float hv[16*132];    // pitch 132 (float4-storable, 2-addr broadcastish)
    __shared__ float qh[16*129];    // pitch 129 (odd -> conflict-free column reads)
    __shared__ float wbuf[4224];    // max(32*129=4128, 128*33=4224)

    const int tid  = threadIdx.x;
    const int row0 = blockIdx.x * 16;

    // Load 16 rows of h_V (16x128 floats) via float4
    {
        const float4* src = (const float4*)(hV + (size_t)row0 * DD);
        for (int i = tid; i < 512; i += 256) {
            int r = i >> 5, c4 = i & 31;
            float4 v = src[i];
            *(float4*)&hv[r*132 + c4*4] = v;
        }
    }

    // ---- Phase Q: qh[r][j] ----
    const int jq = tid & 15;
    const int rq = tid >> 4;     // 0..15 (row)
    for (int jc = 0; jc < DD; jc += 32) {
        __syncthreads();
        // stage WQ rows [jc, jc+32) at pitch 129
        for (int i = tid; i < 32*DD; i += 256) {
            int r = i >> 7, c = i & 127;
            wbuf[r*129 + c] = WQ[(jc + r)*DD + c];
        }
        __syncthreads();
        float a0 = 0.f, a1 = 0.f;
        #pragma unroll 4
        for (int d = 0; d < DD; d++) {
            float hvv = hv[rq*132 + d];
            a0 += hvv * wbuf[jq*129 + d];
            a1 += hvv * wbuf[(jq + 16)*129 + d];
        }
        qh[rq*129 + jc + jq]      = a0;
        qh[rq*129 + jc + jq + 16] = a1;
    }

    // ---- Phase Qp: per head h, Qp[r][h][c] ----
    const int h   = tid >> 6;          // 0..3
    const int sub = tid & 63;
    const int cq  = sub & 7;           // column quad within 32-col chunk
    const int rq2 = sub >> 3;          // 0..7
    const int r0  = rq2 * 2;
    const int c0  = cq * 4;

    for (int cc = 0; cc < DIN; cc += 32) {
        __syncthreads();
        // stage WK[:, cc:cc+32) at pitch 33
        for (int i = tid; i < DD*32; i += 256) {
            int r = i >> 5, c = i & 31;
            wbuf[r*33 + c] = WK[r*DIN + cc + c];
        }
        __syncthreads();
        float acc[2][4] = {};
        #pragma unroll 4
        for (int j = 0; j < 32; j++) {
            int   qc = h*32 + j;
            float q0 = qh[r0*129 + qc];
            float q1 = qh[(r0 + 1)*129 + qc];
            #pragma unroll
            for (int ci = 0; ci < 4; ci++) {
                float wv = wbuf[qc*33 + c0 + ci];
                acc[0][ci] += q0 * wv;
                acc[1][ci] += q1 * wv;
            }
        }
        #pragma unroll
        for (int ri = 0; ri < 2; ri++) {
            float* dst = g_Qp + (size_t)(row0 + r0 + ri)*(HH*DIN) + h*DIN + cc + c0;
            #pragma unroll
            for (int ci = 0; ci < 4; ci++) dst[ci] = acc[ri][ci] * SCALE;
        }
    }
}

// ---------------------------------------------------------------------------
// Kernel 2: one block per (b,n) row. Load E (30x256) + Qp (4x256) -> smem,
// logits -> masked softmax -> weighted E aggregation -> g_Eagg.
// ---------------------------------------------------------------------------
__global__ __launch_bounds__(256) void k2_attn(const float* __restrict__ hE,
                                               const int*   __restrict__ mask)
{
    __shared__ __align__(16) float Es[KKN*DIN];   // 30x256, pitch 256
    __shared__ __align__(16) float Qs[HH*DIN];    // 4x256
    __shared__ float lg[HH][32];
    __shared__ __align__(16) float ws[KKN][4];    // weights transposed (float4 rows)
    __shared__ int   ms[32];

    const int tid = threadIdx.x;
    const int row = blockIdx.x;

    // Load E tile (1920 float4) and Qp row (256 float4)
    {
        const float4* Eg = (const float4*)(hE + (size_t)row * KKN * DIN);
        float4* Es4 = (float4*)Es;
        #pragma unroll 2
        for (int i = tid; i < (KKN*DIN)/4; i += 256) Es4[i] = Eg[i];
        const float4* Qg = (const float4*)(g_Qp + (size_t)row * HH * DIN);
        float4* Qs4 = (float4*)Qs;
        if (tid < (HH*DIN)/4) Qs4[tid] = Qg[tid];
        if (tid < KKN) ms[tid] = mask[row*KKN + tid];
    }
    __syncthreads();

    const int warp = tid >> 5, lane = tid & 31;

    // ---- logits: 120 warp-collective dot products of length 256 ----
    for (int idx = warp; idx < HH*KKN; idx += 8) {
        int h = idx / KKN, k = idx - h*KKN;
        const float4* e4 = (const float4*)(Es + k*DIN);
        const float4* q4 = (const float4*)(Qs + h*DIN);
        float4 ea = e4[lane*2], eb = e4[lane*2 + 1];
        float4 qa = q4[lane*2], qb = q4[lane*2 + 1];
        float s = ea.x*qa.x + ea.y*qa.y + ea.z*qa.z + ea.w*qa.w
                + eb.x*qb.x + eb.y*qb.y + eb.z*qb.z + eb.w*qb.w;
        #pragma unroll
        for (int off = 16; off; off >>= 1) s += __shfl_xor_sync(0xffffffffu, s, off);
        if (lane == 0) lg[h][k] = s;
    }
    __syncthreads();

    // ---- masked softmax per head (one warp per head) ----
    if (warp < HH) {
        int   m = 0;
        float v = -3.0e38f;
        if (lane < KKN) { m = ms[lane]; v = m ? lg[warp][lane] : -3.0e38f; }
        float mx = v;
        #pragma unroll
        for (int off = 16; off; off >>= 1) mx = fmaxf(mx, __shfl_xor_sync(0xffffffffu, mx, off));
        float e  = (lane < KKN) ? expf(v - mx) : 0.f;
        float sm = e;
        #pragma unroll
        for (int off = 16; off; off >>= 1) sm += __shfl_xor_sync(0xffffffffu, sm, off);
        if (lane < KKN) ws[lane][warp] = (e / sm) * (float)m;
    }
    __syncthreads();

    // ---- aggregation: Eagg[h][c] = sum_k w[h][k] * E[k][c] ----
    {
        const int c = tid;  // 0..255
        float acc0 = 0.f, acc1 = 0.f, acc2 = 0.f, acc3 = 0.f;
        #pragma unroll 5
        for (int k = 0; k < KKN; k++) {
            float4 w  = *(const float4*)&ws[k][0];
            float  ev = Es[k*DIN + c];
            acc0 += w.x * ev; acc1 += w.y * ev; acc2 += w.z * ev; acc3 += w.w * ev;
        }
        float* out = g_Eagg + (size_t)row * HH * DIN;
        out[0*DIN + c] = acc0;
        out[1*DIN + c] = acc1;
        out[2*DIN + c] = acc2;
        out[3*DIN + c] = acc3;
    }
}

// ---------------------------------------------------------------------------
// Kernel 3: per-head projection  hu[r][h*32+j] = sum_c WV[h*32+j][c]*Eagg[r][h][c]
// Block: 64 rows x 1 head, K chunked by 32. Register tile 4r x 2j.
// ---------------------------------------------------------------------------
__global__ __launch_bounds__(256) void k3_vproj(const float* __restrict__ WV)
{
    __shared__ float ea[64*33];
    __shared__ float wv[32*33];

    const int tid  = threadIdx.x;
    const int h    = blockIdx.y;
    const int row0 = blockIdx.x * 64;
    const int jq = tid & 15;
    const int rq = tid >> 4;
    const int r0 = rq * 4;
    const int j0 = jq * 2;

    float acc[4][2] = {};
    for (int cc = 0; cc < DIN; cc += 32) {
        __syncthreads();
        for (int i = tid; i < 64*32; i += 256) {
            int r = i >> 5, c = i & 31;
            ea[r*33 + c] = g_Eagg[(size_t)(row0 + r)*(HH*DIN) + h*DIN + cc + c];
        }
        for (int i = tid; i < 32*32; i += 256) {
            int j = i >> 5, c = i & 31;
            wv[j*33 + c] = WV[(h*32 + j)*DIN + cc + c];
        }
        __syncthreads();
        #pragma unroll 4
        for (int c = 0; c < 32; c++) {
            float w0 = wv[j0*33 + c];
            float w1 = wv[(j0 + 1)*33 + c];
            #pragma unroll
            for (int ri = 0; ri < 4; ri++) {
                float ev = ea[(r0 + ri)*33 + c];
                acc[ri][0] += ev * w0;
                acc[ri][1] += ev * w1;
            }
        }
    }
    #pragma unroll
    for (int ri = 0; ri < 4; ri++) {
        float* dst = g_hu + (size_t)(row0 + r0 + ri)*DD + h*32 + j0;
        dst[0] = acc[ri][0];
        dst[1] = acc[ri][1];
    }
}

// ---------------------------------------------------------------------------
// Kernel 4: out[r][j] = sum_d hu[r][d] * WO[j][d]
// Block: 64 rows x 128 cols, K chunked by 32. Register tile 4r x 8j.
// ---------------------------------------------------------------------------
__global__ __launch_bounds__(256) void k4_out(const float* __restrict__ WO,
                                              float* __restrict__ out)
{
    __shared__ float hu[64*33];
    __shared__ float wo[128*33];

    const int tid  = threadIdx.x;
    const int row0 = blockIdx.x * 64;
    const int jq = tid & 15;
    const int rq = tid >> 4;
    const int r0 = rq * 4;

    float acc[4][8] = {};
    for (int dc = 0; dc < DD; dc += 32) {
        __syncthreads();
        for (int i = tid; i < 64*32; i += 256) {
            int r = i >> 5, c = i & 31;
            hu[r*33 + c] = g_hu[(size_t)(row0 + r)*DD + dc + c];
        }
        for (int i = tid; i < 128*32; i += 256) {
            int j = i >> 5, c = i & 31;
            wo[j*33 + c] = WO[j*DD + dc + c];
        }
        __syncthreads();
        #pragma unroll 4
        for (int c = 0; c < 32; c++) {
            float hv0[4];
            #pragma unroll
            for (int ri = 0; ri < 4; ri++) hv0[ri] = hu[(r0 + ri)*33 + c];
            #pragma unroll
            for (int ji = 0; ji < 8; ji++) {
                float w = wo[(jq + 16*ji)*33 + c];
                #pragma unroll
                for (int ri = 0; ri < 4; ri++) acc[ri][ji] += hv0[ri] * w;
            }
        }
    }
    #pragma unroll
    for (int ri = 0; ri < 4; ri++)
        #pragma unroll
        for (int ji = 0; ji < 8; ji++)
            out[(size_t)(row0 + r0 + ri)*DD + jq + 16*ji] = acc[ri][ji];
}

// ---------------------------------------------------------------------------
extern "C" void kernel_launch(void* const* d_in, const int* in_sizes, int n_in,
                              void* d_out, int out_size)
{
    const float* hV   = (const float*)d_in[0];
    const float* hE   = (const float*)d_in[1];
    const int*   mask = (const int*)  d_in[2];
    const float* WQ   = (const float*)d_in[3];
    const float* WK   = (const float*)d_in[4];
    const float* WV   = (const float*)d_in[5];
    const float* WO   = (const float*)d_in[6];
    float*       out  = (float*)d_out;

    k1_qp  <<<ROWS/16, 256>>>(hV, WQ, WK);
    k2_attn<<<ROWS,    256>>>(hE, mask);
    k3_vproj<<<dim3(ROWS/64, HH), 256>>>(WV);
    k4_out <<<ROWS/64, 256>>>(WO, out);
}

// round 6
// speedup vs baseline: 1.0924x; 1.0924x over previous
#include <cuda_runtime.h>
#include <math.h>

// Problem constants
#define BB   4
#define NN   2000
#define KKN  30
#define DD   128
#define DIN  256
#define HH   4
#define ROWS (BB*NN)           // 8000

#define SCALE 0.17677669529663687f   // 1/sqrt(32)

// Scratch (static device globals: no runtime allocation)
__device__ float g_Q   [(size_t)ROWS*DD];      //  4 MB  Q = hV @ WQ^T
__device__ float g_Qp  [(size_t)ROWS*HH*DIN];  // 32 MB  per-head K-projected query
__device__ float g_Eagg[(size_t)ROWS*HH*DIN];  // 32 MB  softmax-weighted E aggregate
__device__ float g_hu  [(size_t)ROWS*DD];      //  4 MB  per-head V projection

// ---------------------------------------------------------------------------
// Kernel Q: Q[r][j] = sum_d hV[r][d] * WQ[j][d]
// 64x64 tile, 256 threads, 4x4 register tile (rows/cols strided by 16).
// grid (125, 2)
// ---------------------------------------------------------------------------
__global__ __launch_bounds__(256) void kQ(const float* __restrict__ hV,
                                          const float* __restrict__ WQ)
{
    __shared__ float as[64*33];
    __shared__ float bs[64*33];

    const int tid  = threadIdx.x;
    const int row0 = blockIdx.x * 64;
    const int col0 = blockIdx.y * 64;
    const int rt   = tid >> 4;   // 0..15
    const int jt   = tid & 15;   // 0..15

    float acc[4][4] = {};
    for (int dc = 0; dc < DD; dc += 32) {
        __syncthreads();
        #pragma unroll
        for (int i = tid; i < 64*32; i += 256) {
            int r = i >> 5, c = i & 31;
            as[r*33 + c] = hV[(size_t)(row0 + r)*DD + dc + c];
            bs[r*33 + c] = WQ[(size_t)(col0 + r)*DD + dc + c];
        }
        __syncthreads();
        #pragma unroll
        for (int c = 0; c < 32; c++) {
            float a[4], b[4];
            #pragma unroll
            for (int m = 0; m < 4; m++) a[m] = as[(rt + 16*m)*33 + c];
            #pragma unroll
            for (int n = 0; n < 4; n++) b[n] = bs[(jt + 16*n)*33 + c];
            #pragma unroll
            for (int m = 0; m < 4; m++)
                #pragma unroll
                for (int n = 0; n < 4; n++) acc[m][n] += a[m]*b[n];
        }
    }
    #pragma unroll
    for (int m = 0; m < 4; m++)
        #pragma unroll
        for (int n = 0; n < 4; n++)
            g_Q[(size_t)(row0 + rt + 16*m)*DD + col0 + jt + 16*n] = acc[m][n];
}

// ---------------------------------------------------------------------------
// Kernel Qp: per head h, Qp[r][h*256+c] = SCALE * sum_{j<32} Q[r][h*32+j]*WK[h*32+j][c]
// K=32 (fully staged). Block: 64 rows x 64 cols, 256 threads, 4x4 tile.
// grid (125, 4 c-chunks, 4 heads)
// ---------------------------------------------------------------------------
__global__ __launch_bounds__(256) void kQp(const float* __restrict__ WK)
{
    __shared__ float qs[64*33];    // [r][j]  j<32
    __shared__ float ws[32*65];    // [j][c]  c<64

    const int tid  = threadIdx.x;
    const int row0 = blockIdx.x * 64;
    const int cc   = blockIdx.y * 64;
    const int h    = blockIdx.z;
    const int rt   = tid >> 4;
    const int ct   = tid & 15;

    // stage Q slice (64 x 32) and WK slice (32 x 64)
    {
        int i = tid;  // 2048 elems, 8 per thread
        #pragma unroll
        for (int it = 0; it < 8; it++, i += 256) {
            int r = i >> 5, j = i & 31;
            qs[r*33 + j] = g_Q[(size_t)(row0 + r)*DD + h*32 + j];
        }
        i = tid;
        #pragma unroll
        for (int it = 0; it < 8; it++, i += 256) {
            int j = i >> 6, c = i & 63;
            ws[j*65 + c] = WK[(size_t)(h*32 + j)*DIN + cc + c];
        }
    }
    __syncthreads();

    float acc[4][4] = {};
    #pragma unroll
    for (int j = 0; j < 32; j++) {
        float a[4], b[4];
        #pragma unroll
        for (int m = 0; m < 4; m++) a[m] = qs[(rt + 16*m)*33 + j];
        #pragma unroll
        for (int n = 0; n < 4; n++) b[n] = ws[j*65 + ct + 16*n];
        #pragma unroll
        for (int m = 0; m < 4; m++)
            #pragma unroll
            for (int n = 0; n < 4; n++) acc[m][n] += a[m]*b[n];
    }
    #pragma unroll
    for (int m = 0; m < 4; m++)
        #pragma unroll
        for (int n = 0; n < 4; n++)
            g_Qp[(size_t)(row0 + rt + 16*m)*(HH*DIN) + h*DIN + cc + ct + 16*n]
                = acc[m][n] * SCALE;
}

// ---------------------------------------------------------------------------
// Kernel 2: one block per (b,n) row. Load E (30x256) + Qp (4x256) -> smem,
// logits -> masked softmax -> weighted E aggregation -> g_Eagg.
// ---------------------------------------------------------------------------
__global__ __launch_bounds__(256) void k2_attn(const float* __restrict__ hE,
                                               const int*   __restrict__ mask)
{
    __shared__ __align__(16) float Es[KKN*DIN];   // 30x256
    __shared__ __align__(16) float Qs[HH*DIN];    // 4x256
    __shared__ float lg[HH][32];
    __shared__ __align__(16) float ws[KKN][4];    // weights transposed
    __shared__ int   ms[32];

    const int tid = threadIdx.x;
    const int row = blockIdx.x;

    {
        // small loads first so their latency hides under the E stream
        if (tid < (HH*DIN)/4) {
            const float4* Qg = (const float4*)(g_Qp + (size_t)row * HH * DIN);
            ((float4*)Qs)[tid] = Qg[tid];
        }
        if (tid < KKN) ms[tid] = mask[row*KKN + tid];

        const float4* Eg = (const float4*)(hE + (size_t)row * KKN * DIN);
        float4* Es4 = (float4*)Es;
        #pragma unroll 2
        for (int i = tid; i < (KKN*DIN)/4; i += 256) Es4[i] = Eg[i];
    }
    __syncthreads();

    const int warp = tid >> 5, lane = tid & 31;

    // logits: 120 warp-collective dots of length 256
    for (int idx = warp; idx < HH*KKN; idx += 8) {
        int h = idx / KKN, k = idx - h*KKN;
        const float4* e4 = (const float4*)(Es + k*DIN);
        const float4* q4 = (const float4*)(Qs + h*DIN);
        float4 ea = e4[lane*2], eb = e4[lane*2 + 1];
        float4 qa = q4[lane*2], qb = q4[lane*2 + 1];
        float s = ea.x*qa.x + ea.y*qa.y + ea.z*qa.z + ea.w*qa.w
                + eb.x*qb.x + eb.y*qb.y + eb.z*qb.z + eb.w*qb.w;
        #pragma unroll
        for (int off = 16; off; off >>= 1) s += __shfl_xor_sync(0xffffffffu, s, off);
        if (lane == 0) lg[h][k] = s;
    }
    __syncthreads();

    // masked softmax per head (one warp per head)
    if (warp < HH) {
        int   m = 0;
        float v = -3.0e38f;
        if (lane < KKN) { m = ms[lane]; v = m ? lg[warp][lane] : -3.0e38f; }
        float mx = v;
        #pragma unroll
        for (int off = 16; off; off >>= 1) mx = fmaxf(mx, __shfl_xor_sync(0xffffffffu, mx, off));
        float e  = (lane < KKN) ? expf(v - mx) : 0.f;
        float sm = e;
        #pragma unroll
        for (int off = 16; off; off >>= 1) sm += __shfl_xor_sync(0xffffffffu, sm, off);
        if (lane < KKN) ws[lane][warp] = (e / sm) * (float)m;
    }
    __syncthreads();

    // aggregation: Eagg[h][c] = sum_k w[h][k] * E[k][c]
    {
        const int c = tid;  // 0..255
        float acc0 = 0.f, acc1 = 0.f, acc2 = 0.f, acc3 = 0.f;
        #pragma unroll 5
        for (int k = 0; k < KKN; k++) {
            float4 w  = *(const float4*)&ws[k][0];
            float  ev = Es[k*DIN + c];
            acc0 += w.x * ev; acc1 += w.y * ev; acc2 += w.z * ev; acc3 += w.w * ev;
        }
        float* out = g_Eagg + (size_t)row * HH * DIN;
        out[0*DIN + c] = acc0;
        out[1*DIN + c] = acc1;
        out[2*DIN + c] = acc2;
        out[3*DIN + c] = acc3;
    }
}

// ---------------------------------------------------------------------------
// Kernel 3: hu[r][h*32+j] = sum_c WV[h*32+j][c] * Eagg[r][h][c]
// Block: 64 rows x 32 j (one head), 128 threads, 4x4 register tile.
// grid (125, 4 heads)
// ---------------------------------------------------------------------------
__global__ __launch_bounds__(128) void k3_vproj(const float* __restrict__ WV)
{
    __shared__ float ea[64*65];    // [r][c] c<64 chunk
    __shared__ float wv[32*65];    // [j][c]

    const int tid  = threadIdx.x;
    const int row0 = blockIdx.x * 64;
    const int h    = blockIdx.y;
    const int rt   = tid >> 3;   // 0..15
    const int jt   = tid & 7;    // 0..7

    float acc[4][4] = {};
    for (int cc = 0; cc < DIN; cc += 64) {
        __syncthreads();
        #pragma unroll
        for (int i = tid; i < 64*64; i += 128) {
            int r = i >> 6, c = i & 63;
            ea[r*65 + c] = g_Eagg[(size_t)(row0 + r)*(HH*DIN) + h*DIN + cc + c];
        }
        #pragma unroll
        for (int i = tid; i < 32*64; i += 128) {
            int j = i >> 6, c = i & 63;
            wv[j*65 + c] = WV[(size_t)(h*32 + j)*DIN + cc + c];
        }
        __syncthreads();
        #pragma unroll 4
        for (int c = 0; c < 64; c++) {
            float a[4], b[4];
            #pragma unroll
            for (int m = 0; m < 4; m++) a[m] = ea[(rt + 16*m)*65 + c];
            #pragma unroll
            for (int n = 0; n < 4; n++) b[n] = wv[(jt + 8*n)*65 + c];
            #pragma unroll
            for (int m = 0; m < 4; m++)
                #pragma unroll
                for (int n = 0; n < 4; n++) acc[m][n] += a[m]*b[n];
        }
    }
    #pragma unroll
    for (int m = 0; m < 4; m++)
        #pragma unroll
        for (int n = 0; n < 4; n++)
            g_hu[(size_t)(row0 + rt + 16*m)*DD + h*32 + jt + 8*n] = acc[m][n];
}

// ---------------------------------------------------------------------------
// Kernel 4: out[r][o] = sum_d hu[r][d] * WO[o][d]
// Same template as kQ. grid (125, 2)
// ---------------------------------------------------------------------------
__global__ __launch_bounds__(256) void k4_out(const float* __restrict__ WO,
                                              float* __restrict__ out)
{
    __shared__ float as[64*33];
    __shared__ float bs[64*33];

    const int tid  = threadIdx.x;
    const int row0 = blockIdx.x * 64;
    const int col0 = blockIdx.y * 64;
    const int rt   = tid >> 4;
    const int jt   = tid & 15;

    float acc[4][4] = {};
    for (int dc = 0; dc < DD; dc += 32) {
        __syncthreads();
        #pragma unroll
        for (int i = tid; i < 64*32; i += 256) {
            int r = i >> 5, c = i & 31;
            as[r*33 + c] = g_hu[(size_t)(row0 + r)*DD + dc + c];
            bs[r*33 + c] = WO[(size_t)(col0 + r)*DD + dc + c];
        }
        __syncthreads();
        #pragma unroll
        for (int c = 0; c < 32; c++) {
            float a[4], b[4];
            #pragma unroll
            for (int m = 0; m < 4; m++) a[m] = as[(rt + 16*m)*33 + c];
            #pragma unroll
            for (int n = 0; n < 4; n++) b[n] = bs[(jt + 16*n)*33 + c];
            #pragma unroll
            for (int m = 0; m < 4; m++)
                #pragma unroll
                for (int n = 0; n < 4; n++) acc[m][n] += a[m]*b[n];
        }
    }
    #pragma unroll
    for (int m = 0; m < 4; m++)
        #pragma unroll
        for (int n = 0; n < 4; n++)
            out[(size_t)(row0 + rt + 16*m)*DD + col0 + jt + 16*n] = acc[m][n];
}

// ---------------------------------------------------------------------------
extern "C" void kernel_launch(void* const* d_in, const int* in_sizes, int n_in,
                              void* d_out, int out_size)
{
    const float* hV   = (const float*)d_in[0];
    const float* hE   = (const float*)d_in[1];
    const int*   mask = (const int*)  d_in[2];
    const float* WQ   = (const float*)d_in[3];
    const float* WK   = (const float*)d_in[4];
    const float* WV   = (const float*)d_in[5];
    const float* WO   = (const float*)d_in[6];
    float*       out  = (float*)d_out;

    kQ     <<<dim3(ROWS/64, 2),      256>>>(hV, WQ);
    kQp    <<<dim3(ROWS/64, 4, HH),  256>>>(WK);
    k2_attn<<<ROWS,                  256>>>(hE, mask);
    k3_vproj<<<dim3(ROWS/64, HH),    128>>>(WV);
    k4_out <<<dim3(ROWS/64, 2),      256>>>(WO, out);
}

// round 7
// speedup vs baseline: 1.1278x; 1.0324x over previous
#include <cuda_runtime.h>
#include <math.h>

// Problem constants
#define BB   4
#define NN   2000
#define KKN  30
#define DD   128
#define DIN  256
#define HH   4
#define ROWS (BB*NN)           // 8000

#define SCALE 0.17677669529663687f   // 1/sqrt(32)

// Scratch (static device globals: no runtime allocation)
__device__ float g_Q   [(size_t)ROWS*DD];      //  4 MB  Q = hV @ WQ^T
__device__ float g_Qp  [(size_t)ROWS*HH*DIN];  // 32 MB  per-head K-projected query
__device__ float g_Eagg[(size_t)ROWS*HH*DIN];  // 32 MB  softmax-weighted E aggregate
__device__ float g_hu  [(size_t)ROWS*DD];      //  4 MB  per-head V projection

// ===========================================================================
// Uniform GEMM template (hand-instantiated): block = 64 rows x 32 cols,
// 256 threads, acc[4][2] (rows rt+16m, cols jt+16n), K chunked by 32 with
// register double-buffered staging.  ~40 regs -> 6 blocks/SM = 48 warps.
// ===========================================================================

// ---------------------------------------------------------------------------
// Kernel Q: Q[r][j] = sum_d hV[r][d] * WQ[j][d].   grid (125, 4)
// ---------------------------------------------------------------------------
__global__ __launch_bounds__(256) void kQ(const float* __restrict__ hV,
                                          const float* __restrict__ WQ)
{
    __shared__ float as[64*33];
    __shared__ float bs[32*33];

    const int tid  = threadIdx.x;
    const int row0 = blockIdx.x * 64;
    const int col0 = blockIdx.y * 32;
    const int rt   = tid >> 4;   // 0..15
    const int jt   = tid & 15;   // 0..15

    float ra[8], rb[4];
    // prefetch chunk 0
    #pragma unroll
    for (int it = 0; it < 8; it++) {
        int i = tid + 256*it;
        ra[it] = hV[(size_t)(row0 + (i >> 5))*DD + (i & 31)];
    }
    #pragma unroll
    for (int it = 0; it < 4; it++) {
        int i = tid + 256*it;
        rb[it] = WQ[(size_t)(col0 + (i >> 5))*DD + (i & 31)];
    }

    float acc[4][2] = {};
    for (int dc = 0; dc < DD; dc += 32) {
        __syncthreads();
        #pragma unroll
        for (int it = 0; it < 8; it++) {
            int i = tid + 256*it;
            as[(i >> 5)*33 + (i & 31)] = ra[it];
        }
        #pragma unroll
        for (int it = 0; it < 4; it++) {
            int i = tid + 256*it;
            bs[(i >> 5)*33 + (i & 31)] = rb[it];
        }
        __syncthreads();
        if (dc + 32 < DD) {
            #pragma unroll
            for (int it = 0; it < 8; it++) {
                int i = tid + 256*it;
                ra[it] = hV[(size_t)(row0 + (i >> 5))*DD + dc + 32 + (i & 31)];
            }
            #pragma unroll
            for (int it = 0; it < 4; it++) {
                int i = tid + 256*it;
                rb[it] = WQ[(size_t)(col0 + (i >> 5))*DD + dc + 32 + (i & 31)];
            }
        }
        #pragma unroll
        for (int c = 0; c < 32; c++) {
            float a[4], b[2];
            #pragma unroll
            for (int m = 0; m < 4; m++) a[m] = as[(rt + 16*m)*33 + c];
            #pragma unroll
            for (int n = 0; n < 2; n++) b[n] = bs[(jt + 16*n)*33 + c];
            #pragma unroll
            for (int m = 0; m < 4; m++)
                #pragma unroll
                for (int n = 0; n < 2; n++) acc[m][n] += a[m]*b[n];
        }
    }
    #pragma unroll
    for (int m = 0; m < 4; m++)
        #pragma unroll
        for (int n = 0; n < 2; n++)
            g_Q[(size_t)(row0 + rt + 16*m)*DD + col0 + jt + 16*n] = acc[m][n];
}

// ---------------------------------------------------------------------------
// Kernel Qp: per head h, Qp[r][h*256+c] = SCALE * sum_{j<32} Q[r][h*32+j]*WK[h*32+j][c]
// K=32 fully staged. Block: 64 rows x 64 cols, 256 threads, 4x4 tile.
// grid (125, 4 c-chunks, 4 heads)
// ---------------------------------------------------------------------------
__global__ __launch_bounds__(256) void kQp(const float* __restrict__ WK)
{
    __shared__ float qs[64*33];    // [r][j]  j<32
    __shared__ float ws[32*65];    // [j][c]  c<64

    const int tid  = threadIdx.x;
    const int row0 = blockIdx.x * 64;
    const int cc   = blockIdx.y * 64;
    const int h    = blockIdx.z;
    const int rt   = tid >> 4;
    const int ct   = tid & 15;

    {
        int i = tid;
        #pragma unroll
        for (int it = 0; it < 8; it++, i += 256) {
            int r = i >> 5, j = i & 31;
            qs[r*33 + j] = g_Q[(size_t)(row0 + r)*DD + h*32 + j];
        }
        i = tid;
        #pragma unroll
        for (int it = 0; it < 8; it++, i += 256) {
            int j = i >> 6, c = i & 63;
            ws[j*65 + c] = WK[(size_t)(h*32 + j)*DIN + cc + c];
        }
    }
    __syncthreads();

    float acc[4][4] = {};
    #pragma unroll
    for (int j = 0; j < 32; j++) {
        float a[4], b[4];
        #pragma unroll
        for (int m = 0; m < 4; m++) a[m] = qs[(rt + 16*m)*33 + j];
        #pragma unroll
        for (int n = 0; n < 4; n++) b[n] = ws[j*65 + ct + 16*n];
        #pragma unroll
        for (int m = 0; m < 4; m++)
            #pragma unroll
            for (int n = 0; n < 4; n++) acc[m][n] += a[m]*b[n];
    }
    #pragma unroll
    for (int m = 0; m < 4; m++)
        #pragma unroll
        for (int n = 0; n < 4; n++)
            g_Qp[(size_t)(row0 + rt + 16*m)*(HH*DIN) + h*DIN + cc + ct + 16*n]
                = acc[m][n] * SCALE;
}

// ---------------------------------------------------------------------------
// Kernel 2: one block per (b,n) row. Load E (30x256) + Qp (4x256) -> smem,
// logits -> masked softmax -> weighted E aggregation -> g_Eagg.
// ---------------------------------------------------------------------------
__global__ __launch_bounds__(256) void k2_attn(const float* __restrict__ hE,
                                               const int*   __restrict__ mask)
{
    __shared__ __align__(16) float Es[KKN*DIN];   // 30x256
    __shared__ __align__(16) float Qs[HH*DIN];    // 4x256
    __shared__ float lg[HH][32];
    __shared__ __align__(16) float ws[KKN][4];    // weights transposed
    __shared__ int   ms[32];

    const int tid = threadIdx.x;
    const int row = blockIdx.x;

    {
        // small loads first so their latency hides under the E stream
        if (tid < (HH*DIN)/4) {
            const float4* Qg = (const float4*)(g_Qp + (size_t)row * HH * DIN);
            ((float4*)Qs)[tid] = Qg[tid];
        }
        if (tid < KKN) ms[tid] = mask[row*KKN + tid];

        const float4* Eg = (const float4*)(hE + (size_t)row * KKN * DIN);
        float4* Es4 = (float4*)Es;
        #pragma unroll 4
        for (int i = tid; i < (KKN*DIN)/4; i += 256) Es4[i] = Eg[i];
    }
    __syncthreads();

    const int warp = tid >> 5, lane = tid & 31;

    // logits: 120 warp-collective dots of length 256
    for (int idx = warp; idx < HH*KKN; idx += 8) {
        int h = idx / KKN, k = idx - h*KKN;
        const float4* e4 = (const float4*)(Es + k*DIN);
        const float4* q4 = (const float4*)(Qs + h*DIN);
        float4 ea = e4[lane*2], eb = e4[lane*2 + 1];
        float4 qa = q4[lane*2], qb = q4[lane*2 + 1];
        float s = ea.x*qa.x + ea.y*qa.y + ea.z*qa.z + ea.w*qa.w
                + eb.x*qb.x + eb.y*qb.y + eb.z*qb.z + eb.w*qb.w;
        #pragma unroll
        for (int off = 16; off; off >>= 1) s += __shfl_xor_sync(0xffffffffu, s, off);
        if (lane == 0) lg[h][k] = s;
    }
    __syncthreads();

    // masked softmax per head (one warp per head)
    if (warp < HH) {
        int   m = 0;
        float v = -3.0e38f;
        if (lane < KKN) { m = ms[lane]; v = m ? lg[warp][lane] : -3.0e38f; }
        float mx = v;
        #pragma unroll
        for (int off = 16; off; off >>= 1) mx = fmaxf(mx, __shfl_xor_sync(0xffffffffu, mx, off));
        float e  = (lane < KKN) ? expf(v - mx) : 0.f;
        float sm = e;
        #pragma unroll
        for (int off = 16; off; off >>= 1) sm += __shfl_xor_sync(0xffffffffu, sm, off);
        if (lane < KKN) ws[lane][warp] = (e / sm) * (float)m;
    }
    __syncthreads();

    // aggregation: Eagg[h][c] = sum_k w[h][k] * E[k][c]
    {
        const int c = tid;  // 0..255
        float acc0 = 0.f, acc1 = 0.f, acc2 = 0.f, acc3 = 0.f;
        #pragma unroll 5
        for (int k = 0; k < KKN; k++) {
            float4 w  = *(const float4*)&ws[k][0];
            float  ev = Es[k*DIN + c];
            acc0 += w.x * ev; acc1 += w.y * ev; acc2 += w.z * ev; acc3 += w.w * ev;
        }
        float* out = g_Eagg + (size_t)row * HH * DIN;
        out[0*DIN + c] = acc0;
        out[1*DIN + c] = acc1;
        out[2*DIN + c] = acc2;
        out[3*DIN + c] = acc3;
    }
}

// ---------------------------------------------------------------------------
// Kernel 3: hu[r][h*32+j] = sum_c WV[h*32+j][c] * Eagg[r][h][c]
// Template: 64 rows x 32 j (one head), 256 threads, acc[4][2], K=256 chunk 32,
// double-buffered. grid (125, 4 heads)
// ---------------------------------------------------------------------------
__global__ __launch_bounds__(256) void k3_vproj(const float* __restrict__ WV)
{
    __shared__ float as[64*33];
    __shared__ float bs[32*33];

    const int tid  = threadIdx.x;
    const int row0 = blockIdx.x * 64;
    const int h    = blockIdx.y;
    const int rt   = tid >> 4;
    const int jt   = tid & 15;

    const float* A = g_Eagg + (size_t)h * DIN;          // + row*(HH*DIN) + c
    const float* Bw = WV + (size_t)h * 32 * DIN;        // rows j<32

    float ra[8], rb[4];
    #pragma unroll
    for (int it = 0; it < 8; it++) {
        int i = tid + 256*it;
        ra[it] = A[(size_t)(row0 + (i >> 5))*(HH*DIN) + (i & 31)];
    }
    #pragma unroll
    for (int it = 0; it < 4; it++) {
        int i = tid + 256*it;
        rb[it] = Bw[(size_t)(i >> 5)*DIN + (i & 31)];
    }

    float acc[4][2] = {};
    for (int cc = 0; cc < DIN; cc += 32) {
        __syncthreads();
        #pragma unroll
        for (int it = 0; it < 8; it++) {
            int i = tid + 256*it;
            as[(i >> 5)*33 + (i & 31)] = ra[it];
        }
        #pragma unroll
        for (int it = 0; it < 4; it++) {
            int i = tid + 256*it;
            bs[(i >> 5)*33 + (i & 31)] = rb[it];
        }
        __syncthreads();
        if (cc + 32 < DIN) {
            #pragma unroll
            for (int it = 0; it < 8; it++) {
                int i = tid + 256*it;
                ra[it] = A[(size_t)(row0 + (i >> 5))*(HH*DIN) + cc + 32 + (i & 31)];
            }
            #pragma unroll
            for (int it = 0; it < 4; it++) {
                int i = tid + 256*it;
                rb[it] = Bw[(size_t)(i >> 5)*DIN + cc + 32 + (i & 31)];
            }
        }
        #pragma unroll
        for (int c = 0; c < 32; c++) {
            float a[4], b[2];
            #pragma unroll
            for (int m = 0; m < 4; m++) a[m] = as[(rt + 16*m)*33 + c];
            #pragma unroll
            for (int n = 0; n < 2; n++) b[n] = bs[(jt + 16*n)*33 + c];
            #pragma unroll
            for (int m = 0; m < 4; m++)
                #pragma unroll
                for (int n = 0; n < 2; n++) acc[m][n] += a[m]*b[n];
        }
    }
    #pragma unroll
    for (int m = 0; m < 4; m++)
        #pragma unroll
        for (int n = 0; n < 2; n++)
            g_hu[(size_t)(row0 + rt + 16*m)*DD + h*32 + jt + 16*n] = acc[m][n];
}

// ---------------------------------------------------------------------------
// Kernel 4: out[r][o] = sum_d hu[r][d] * WO[o][d]
// Template: 64 rows x 32 cols, grid (125, 4), double-buffered.
// ---------------------------------------------------------------------------
__global__ __launch_bounds__(256) void k4_out(const float* __restrict__ WO,
                                              float* __restrict__ out)
{
    __shared__ float as[64*33];
    __shared__ float bs[32*33];

    const int tid  = threadIdx.x;
    const int row0 = blockIdx.x * 64;
    const int col0 = blockIdx.y * 32;
    const int rt   = tid >> 4;
    const int jt   = tid & 15;

    float ra[8], rb[4];
    #pragma unroll
    for (int it = 0; it < 8; it++) {
        int i = tid + 256*it;
        ra[it] = g_hu[(size_t)(row0 + (i >> 5))*DD + (i & 31)];
    }
    #pragma unroll
    for (int it = 0; it < 4; it++) {
        int i = tid + 256*it;
        rb[it] = WO[(size_t)(col0 + (i >> 5))*DD + (i & 31)];
    }

    float acc[4][2] = {};
    for (int dc = 0; dc < DD; dc += 32) {
        __syncthreads();
        #pragma unroll
        for (int it = 0; it < 8; it++) {
            int i = tid + 256*it;
            as[(i >> 5)*33 + (i & 31)] = ra[it];
        }
        #pragma unroll
        for (int it = 0; it < 4; it++) {
            int i = tid + 256*it;
            bs[(i >> 5)*33 + (i & 31)] = rb[it];
        }
        __syncthreads();
        if (dc + 32 < DD) {
            #pragma unroll
            for (int it = 0; it < 8; it++) {
                int i = tid + 256*it;
                ra[it] = g_hu[(size_t)(row0 + (i >> 5))*DD + dc + 32 + (i & 31)];
            }
            #pragma unroll
            for (int it = 0; it < 4; it++) {
                int i = tid + 256*it;
                rb[it] = WO[(size_t)(col0 + (i >> 5))*DD + dc + 32 + (i & 31)];
            }
        }
        #pragma unroll
        for (int c = 0; c < 32; c++) {
            float a[4], b[2];
            #pragma unroll
            for (int m = 0; m < 4; m++) a[m] = as[(rt + 16*m)*33 + c];
            #pragma unroll
            for (int n = 0; n < 2; n++) b[n] = bs[(jt + 16*n)*33 + c];
            #pragma unroll
            for (int m = 0; m < 4; m++)
                #pragma unroll
                for (int n = 0; n < 2; n++) acc[m][n] += a[m]*b[n];
        }
    }
    #pragma unroll
    for (int m = 0; m < 4; m++)
        #pragma unroll
        for (int n = 0; n < 2; n++)
            out[(size_t)(row0 + rt + 16*m)*DD + col0 + jt + 16*n] = acc[m][n];
}

// ---------------------------------------------------------------------------
extern "C" void kernel_launch(void* const* d_in, const int* in_sizes, int n_in,
                              void* d_out, int out_size)
{
    const float* hV   = (const float*)d_in[0];
    const float* hE   = (const float*)d_in[1];
    const int*   mask = (const int*)  d_in[2];
    const float* WQ   = (const float*)d_in[3];
    const float* WK   = (const float*)d_in[4];
    const float* WV   = (const float*)d_in[5];
    const float* WO   = (const float*)d_in[6];
    float*       out  = (float*)d_out;

    kQ     <<<dim3(ROWS/64, 4),      256>>>(hV, WQ);
    kQp    <<<dim3(ROWS/64, 4, HH),  256>>>(WK);
    k2_attn<<<ROWS,                  256>>>(hE, mask);
    k3_vproj<<<dim3(ROWS/64, HH),    256>>>(WV);
    k4_out <<<dim3(ROWS/64, 4),      256>>>(WO, out);
}